// round 15
// baseline (speedup 1.0000x reference)
#include <cuda_runtime.h>
#include <cstdint>

#define THREADS 128
#define ROWS 128                         // rows per block (== THREADS)
#define UNITS 8                          // 16B units per row per chunk
#define NCHUNK 4                         // D=128 floats / 32 per chunk
#define STAGE_UNITS (2 * ROWS * UNITS)   // X rows then theta rows: 2048 float4
#define STAGE_BYTES (STAGE_UNITS * 16)   // 32768 B
#define NSTAGE 3

#define XI_OFF   (NSTAGE * STAGE_BYTES)       // 64 float4  (1KB)
#define TH_OFF   (XI_OFF + 1024)              // theta halo row: 32 float4 (512B)
#define V_OFF    (TH_OFF + 512)               // V exchange: 129 float2
#define SMEM_TOTAL (V_OFF + 129 * 8 + 8)

__device__ __forceinline__ void cp_async16(uint32_t dst_smem, const void* src) {
    asm volatile("cp.async.cg.shared.global [%0], [%1], 16;\n"
                 :: "r"(dst_smem), "l"(src));
}
__device__ __forceinline__ void cp_commit() {
    asm volatile("cp.async.commit_group;\n");
}
template <int NN>
__device__ __forceinline__ void cp_wait() {
    asm volatile("cp.async.wait_group %0;\n" :: "n"(NN));
}

__device__ __forceinline__ float dot4(float4 a, float4 b) {
    return a.x*b.x + a.y*b.y + a.z*b.z + a.w*b.w;
}
__device__ __forceinline__ void acc4(float& a, float4 x, float4 y) {
    a = fmaf(x.x, y.x, a);
    a = fmaf(x.y, y.y, a);
    a = fmaf(x.z, y.z, a);
    a = fmaf(x.w, y.w, a);
}

__global__ __launch_bounds__(THREADS)
void smf_kernel(const float* __restrict__ X,
                const float* __restrict__ theta,
                const float* __restrict__ f_bias,
                const float* __restrict__ xi,
                const float* __restrict__ g_bias,
                float* __restrict__ out,
                int N)
{
    extern __shared__ char smem[];
    float4* __restrict__ buf = reinterpret_cast<float4*>(smem);
    float4* __restrict__ xis = reinterpret_cast<float4*>(smem + XI_OFF);
    float4* __restrict__ thh = reinterpret_cast<float4*>(smem + TH_OFF);
    float2* __restrict__ vsh = reinterpret_cast<float2*>(smem + V_OFF);

    const int tid  = threadIdx.x;
    const int base = blockIdx.x * ROWS;

    const float4* __restrict__ X4  = reinterpret_cast<const float4*>(X);
    const float4* __restrict__ T4  = reinterpret_cast<const float4*>(theta);
    const float4* __restrict__ XI4 = reinterpret_cast<const float4*>(xi);

    const uint32_t sb = (uint32_t)__cvta_generic_to_shared(smem);

    int hrow = base + ROWS;
    if (hrow >= N) hrow -= N;

    // One-time smem fills (visible after first in-loop __syncthreads)
    if (tid < 64) {
        xis[tid] = XI4[tid];
    } else if (tid < 96) {
        thh[tid - 64] = T4[(size_t)hrow * 32 + (tid - 64)];
    }

    // X-halo loads issued early; reduced at the very end (warp 0 only)
    float4 xh, hw0, hw1;
    if (tid < 32) {
        xh  = __ldg(X4 + (size_t)hrow * 32 + tid);
        hw0 = __ldg(XI4 + tid);
        hw1 = __ldg(XI4 + 32 + tid);
    }

    // Per-thread invariant issue geometry: idx = tid + 128k -> row = r0+16k,
    // u const, and (row & 7) == (r0 & 7) so the swizzle XOR is constant.
    const int r0 = tid >> 3;        // 0..15
    const int u  = tid & 7;
    const int su = u ^ (r0 & 7);

    auto issue = [&](int c, int s) {
        const float4* xsrc = X4 + (size_t)(base + r0) * 32 + c * UNITS + u;
        const float4* tsrc = T4 + (size_t)(base + r0) * 32 + c * UNITS + u;
        const uint32_t xd = sb + (uint32_t)s * STAGE_BYTES + (uint32_t)(r0 * UNITS + su) * 16;
        const uint32_t td = xd + (uint32_t)(ROWS * UNITS) * 16;
        #pragma unroll
        for (int k = 0; k < 8; k++) {
            cp_async16(xd + (uint32_t)k * 2048, xsrc + (size_t)k * 512);
            cp_async16(td + (uint32_t)k * 2048, tsrc + (size_t)k * 512);
        }
        cp_commit();
    };

    float pd = 0.0f, ps = 0.0f, q0 = 0.0f, q1 = 0.0f;

    const int mx = tid & 7;              // swizzle xor for x / theta-diag rows

    auto compute = [&](int c, int s) {
        const float4* __restrict__ st = buf + s * STAGE_UNITS;
        const float4* __restrict__ xrow = st + tid * UNITS;
        const float4* __restrict__ trow = st + (ROWS + tid) * UNITS;

        const float4* sptr;
        int sxor;
        if (tid < ROWS - 1) { sptr = st + (ROWS + tid + 1) * UNITS; sxor = (tid + 1) & 7; }
        else                { sptr = thh + c * UNITS;               sxor = 0; }

        #pragma unroll
        for (int uu = 0; uu < UNITS; uu++) {
            float4 xv = xrow[uu ^ mx];
            float4 td = trow[uu ^ mx];
            float4 ts = sptr[uu ^ sxor];
            float4 w0 = xis[c * UNITS + uu];         // broadcast
            float4 w1 = xis[32 + c * UNITS + uu];    // broadcast
            acc4(pd, xv, td);
            acc4(ps, xv, ts);
            acc4(q0, xv, w0);
            acc4(q1, xv, w1);
        }
    };

    // ---- 3-stage pipeline, 2 outstanding groups ----
    issue(0, 0);
    issue(1, 1);
    issue(2, 2);

    cp_wait<2>(); __syncthreads();
    compute(0, 0);
    __syncthreads();            // stage 0 free for chunk 3
    issue(3, 0);

    cp_wait<2>(); __syncthreads();
    compute(1, 1);

    cp_wait<1>(); __syncthreads();
    compute(2, 2);

    cp_wait<0>(); __syncthreads();
    compute(3, 0);

    // ---- Epilogue ----
    const float gb0 = g_bias[0];
    const float gb1 = g_bias[1];

    const int i = base + tid;
    int in = i + 1;
    if (in >= N) in -= N;

    const float wd = fmaxf(pd + __ldg(f_bias + i),  0.0f);
    const float ws = fmaxf(ps + __ldg(f_bias + in), 0.0f);
    const float v0 = fmaxf(q0 + gb0, 0.0f);
    const float v1 = fmaxf(q1 + gb1, 0.0f);
    vsh[tid] = make_float2(v0, v1);

    // Halo V (warp 0): loads were issued at kernel start
    if (tid < 32) {
        float h0 = dot4(xh, hw0);
        float h1 = dot4(xh, hw1);
        #pragma unroll
        for (int o = 16; o > 0; o >>= 1) {
            h0 += __shfl_xor_sync(0xFFFFFFFFu, h0, o);
            h1 += __shfl_xor_sync(0xFFFFFFFFu, h1, o);
        }
        if (tid == 0)
            vsh[ROWS] = make_float2(fmaxf(h0 + gb0, 0.0f), fmaxf(h1 + gb1, 0.0f));
    }
    __syncthreads();

    const float2 vn = vsh[tid + 1];
    float2 o;
    o.x = wd * v0 + ws * vn.x;
    o.y = wd * v1 + ws * vn.y;
    reinterpret_cast<float2*>(out)[i] = o;
}

extern "C" void kernel_launch(void* const* d_in, const int* in_sizes, int n_in,
                              void* d_out, int out_size)
{
    const float* X      = (const float*)d_in[0];
    const float* theta  = (const float*)d_in[1];
    const float* f_bias = (const float*)d_in[2];
    const float* xi     = (const float*)d_in[3];
    const float* g_bias = (const float*)d_in[4];
    float* out = (float*)d_out;

    const int N = in_sizes[2];            // f_bias has N elements
    const int blocks = N / ROWS;          // 524288 / 128 = 4096

    cudaFuncSetAttribute(smf_kernel,
                         cudaFuncAttributeMaxDynamicSharedMemorySize,
                         SMEM_TOTAL);

    smf_kernel<<<blocks, THREADS, SMEM_TOTAL>>>(X, theta, f_bias, xi, g_bias, out, N);
}

// round 16
// speedup vs baseline: 1.0052x; 1.0052x over previous
#include <cuda_runtime.h>
#include <cstdint>

#define THREADS 128
#define ROWS 128                          // rows per block (== THREADS)
#define CUNITS 4                          // 16B units per row per chunk (16 floats)
#define NCHUNK 8                          // D=128 floats / 16 per chunk
#define STAGE_UNITS (2 * ROWS * CUNITS)   // X rows then theta rows: 1024 float4
#define STAGE_BYTES (STAGE_UNITS * 16)    // 16384 B
#define NSTAGE 4

#define XI_OFF   (NSTAGE * STAGE_BYTES)        // 64 float4 (1KB)
#define TH_OFF   (XI_OFF + 1024)               // theta halo row: 32 float4 (512B)
#define V_OFF    (TH_OFF + 512)                // V exchange: 129 float2
#define SMEM_TOTAL (V_OFF + 129 * 8 + 8)

__device__ __forceinline__ void cp_async16(uint32_t dst_smem, const void* src) {
    asm volatile("cp.async.cg.shared.global [%0], [%1], 16;\n"
                 :: "r"(dst_smem), "l"(src));
}
__device__ __forceinline__ void cp_commit() {
    asm volatile("cp.async.commit_group;\n");
}
template <int NN>
__device__ __forceinline__ void cp_wait() {
    asm volatile("cp.async.wait_group %0;\n" :: "n"(NN));
}

__device__ __forceinline__ float dot4(float4 a, float4 b) {
    return a.x*b.x + a.y*b.y + a.z*b.z + a.w*b.w;
}
__device__ __forceinline__ void acc4(float& a, float4 x, float4 y) {
    a = fmaf(x.x, y.x, a);
    a = fmaf(x.y, y.y, a);
    a = fmaf(x.z, y.z, a);
    a = fmaf(x.w, y.w, a);
}

__global__ __launch_bounds__(THREADS)
void smf_kernel(const float* __restrict__ X,
                const float* __restrict__ theta,
                const float* __restrict__ f_bias,
                const float* __restrict__ xi,
                const float* __restrict__ g_bias,
                float* __restrict__ out,
                int N)
{
    extern __shared__ char smem[];
    float4* __restrict__ buf = reinterpret_cast<float4*>(smem);
    float4* __restrict__ xis = reinterpret_cast<float4*>(smem + XI_OFF);
    float4* __restrict__ thh = reinterpret_cast<float4*>(smem + TH_OFF);
    float2* __restrict__ vsh = reinterpret_cast<float2*>(smem + V_OFF);

    const int tid  = threadIdx.x;
    const int base = blockIdx.x * ROWS;

    const float4* __restrict__ X4  = reinterpret_cast<const float4*>(X);
    const float4* __restrict__ T4  = reinterpret_cast<const float4*>(theta);
    const float4* __restrict__ XI4 = reinterpret_cast<const float4*>(xi);

    const uint32_t sb = (uint32_t)__cvta_generic_to_shared(smem);

    int hrow = base + ROWS;
    if (hrow >= N) hrow -= N;

    // One-time smem fills (visible after the first in-loop __syncthreads)
    if (tid < 64) {
        xis[tid] = XI4[tid];
    } else if (tid < 96) {
        thh[tid - 64] = T4[(size_t)hrow * 32 + (tid - 64)];
    }

    // X-halo loads issued early; reduced at the very end (warp 0 only)
    float4 xh, hw0, hw1;
    if (tid < 32) {
        xh  = __ldg(X4 + (size_t)hrow * 32 + tid);
        hw0 = __ldg(XI4 + tid);
        hw1 = __ldg(XI4 + 32 + tid);
    }

    // ---- Issue geometry (per-thread loop-invariant swizzle) ----
    // idx = tid + 128k -> row = r0 + 32k, u const.
    // Within a 128B line (2 rows): pu = ((row&1)<<2 | u) ^ ((row>>1)&7).
    // (row&1) and ((row>>1)&7) are k-invariant since 32k is even and 16k%8==0.
    const int r0 = tid >> 2;        // 0..31
    const int u  = tid & 3;
    const int pu = (((r0 & 1) << 2) | u) ^ ((r0 >> 1) & 7);
    const int l0 = r0 >> 1;         // line 0..15

    auto issue = [&](int c, int s) {
        const float4* xsrc = X4 + (size_t)(base + r0) * 32 + c * CUNITS + u;
        const float4* tsrc = T4 + (size_t)(base + r0) * 32 + c * CUNITS + u;
        const uint32_t xd = sb + (uint32_t)s * STAGE_BYTES
                               + (uint32_t)l0 * 128 + (uint32_t)pu * 16;
        const uint32_t td = xd + 8192;   // theta half of the stage
        #pragma unroll
        for (int k = 0; k < 4; k++) {    // rows r0+32k, k=0..3 -> 128 rows
            cp_async16(xd + (uint32_t)k * 2048, xsrc + (size_t)k * 1024);
            cp_async16(td + (uint32_t)k * 2048, tsrc + (size_t)k * 1024);
        }
        cp_commit();
    };

    float pd = 0.0f, ps = 0.0f, q0 = 0.0f, q1 = 0.0f;

    // Compute-side swizzle constants
    const int mxor = ((tid & 1) << 2) ^ ((tid >> 1) & 7);          // X / theta-diag
    const int lx   = tid >> 1;                                      // line of row tid
    const int lt   = (tid + 1) >> 1;                                // line of row tid+1
    const int sxor0 = (((tid + 1) & 1) << 2) ^ (((tid + 1) >> 1) & 7);

    auto compute = [&](int c, int s) {
        const float4* __restrict__ st   = buf + s * STAGE_UNITS;
        const float4* __restrict__ xrow = st + lx * 8;
        const float4* __restrict__ trow = st + 512 + lx * 8;   // +8192B

        const float4* sptr;
        int sxor;
        if (tid < ROWS - 1) { sptr = st + 512 + lt * 8; sxor = sxor0; }
        else                { sptr = thh + c * CUNITS; sxor = 0; }

        #pragma unroll
        for (int uu = 0; uu < CUNITS; uu++) {
            float4 xv = xrow[uu ^ mxor];
            float4 td = trow[uu ^ mxor];
            float4 ts = sptr[uu ^ sxor];
            float4 w0 = xis[c * CUNITS + uu];          // broadcast
            float4 w1 = xis[32 + c * CUNITS + uu];     // broadcast
            acc4(pd, xv, td);
            acc4(ps, xv, ts);
            acc4(q0, xv, w0);
            acc4(q1, xv, w1);
        }
    };

    // ---- 4-stage pipeline, 3 outstanding groups, issue-before-compute ----
    issue(0, 0);
    issue(1, 1);
    issue(2, 2);

    #pragma unroll
    for (int c = 0; c < NCHUNK; c++) {
        if (c < NCHUNK - 2)      cp_wait<2>();
        else if (c == NCHUNK - 2) cp_wait<1>();
        else                      cp_wait<0>();
        __syncthreads();   // chunk c visible; all threads done with compute(c-1)
        if (c + 3 < NCHUNK)
            issue(c + 3, (c + 3) & 3);   // writes stage of chunk c-1 (safe)
        compute(c, c & 3);
    }

    // ---- Epilogue ----
    const float gb0 = g_bias[0];
    const float gb1 = g_bias[1];

    const int i = base + tid;
    int in = i + 1;
    if (in >= N) in -= N;

    const float wd = fmaxf(pd + __ldg(f_bias + i),  0.0f);
    const float ws = fmaxf(ps + __ldg(f_bias + in), 0.0f);
    const float v0 = fmaxf(q0 + gb0, 0.0f);
    const float v1 = fmaxf(q1 + gb1, 0.0f);
    vsh[tid] = make_float2(v0, v1);

    // Halo V (warp 0): loads were issued at kernel start
    if (tid < 32) {
        float h0 = dot4(xh, hw0);
        float h1 = dot4(xh, hw1);
        #pragma unroll
        for (int o = 16; o > 0; o >>= 1) {
            h0 += __shfl_xor_sync(0xFFFFFFFFu, h0, o);
            h1 += __shfl_xor_sync(0xFFFFFFFFu, h1, o);
        }
        if (tid == 0)
            vsh[ROWS] = make_float2(fmaxf(h0 + gb0, 0.0f), fmaxf(h1 + gb1, 0.0f));
    }
    __syncthreads();

    const float2 vn = vsh[tid + 1];
    float2 o;
    o.x = wd * v0 + ws * vn.x;
    o.y = wd * v1 + ws * vn.y;
    reinterpret_cast<float2*>(out)[i] = o;
}

extern "C" void kernel_launch(void* const* d_in, const int* in_sizes, int n_in,
                              void* d_out, int out_size)
{
    const float* X      = (const float*)d_in[0];
    const float* theta  = (const float*)d_in[1];
    const float* f_bias = (const float*)d_in[2];
    const float* xi     = (const float*)d_in[3];
    const float* g_bias = (const float*)d_in[4];
    float* out = (float*)d_out;

    const int N = in_sizes[2];            // f_bias has N elements
    const int blocks = N / ROWS;          // 524288 / 128 = 4096

    cudaFuncSetAttribute(smf_kernel,
                         cudaFuncAttributeMaxDynamicSharedMemorySize,
                         SMEM_TOTAL);

    smf_kernel<<<blocks, THREADS, SMEM_TOTAL>>>(X, theta, f_bias, xi, g_bias, out, N);
}

// round 17
// speedup vs baseline: 1.0534x; 1.0479x over previous
#include <cuda_runtime.h>
#include <cstdint>

#define THREADS 64
#define ROWS 64                          // rows per block (== THREADS)
#define UNITS 8                          // 16B units per row per chunk
#define NCHUNK 4                         // D=128 floats / 32 per chunk
#define STAGE_UNITS (2 * ROWS * UNITS)   // X rows then theta rows: 1024 float4
#define STAGE_BYTES (STAGE_UNITS * 16)   // 16384 B

#define XI_OFF   (2 * STAGE_BYTES)            // 64 float4  (1KB)
#define TH_OFF   (XI_OFF + 1024)              // theta halo row: 32 float4 (512B)
#define V_OFF    (TH_OFF + 512)               // V exchange: 65 float2
#define SMEM_TOTAL (V_OFF + 65 * 8 + 8)

__device__ __forceinline__ void cp_async16(uint32_t dst_smem, const void* src) {
    asm volatile("cp.async.cg.shared.global [%0], [%1], 16;\n"
                 :: "r"(dst_smem), "l"(src));
}
__device__ __forceinline__ void cp_commit() {
    asm volatile("cp.async.commit_group;\n");
}
template <int NN>
__device__ __forceinline__ void cp_wait() {
    asm volatile("cp.async.wait_group %0;\n" :: "n"(NN));
}

__device__ __forceinline__ float dot4(float4 a, float4 b) {
    return a.x*b.x + a.y*b.y + a.z*b.z + a.w*b.w;
}
__device__ __forceinline__ void acc4(float& a, float4 x, float4 y) {
    a = fmaf(x.x, y.x, a);
    a = fmaf(x.y, y.y, a);
    a = fmaf(x.z, y.z, a);
    a = fmaf(x.w, y.w, a);
}

__global__ __launch_bounds__(THREADS)
void smf_kernel(const float* __restrict__ X,
                const float* __restrict__ theta,
                const float* __restrict__ f_bias,
                const float* __restrict__ xi,
                const float* __restrict__ g_bias,
                float* __restrict__ out,
                int N)
{
    extern __shared__ char smem[];
    float4* __restrict__ buf = reinterpret_cast<float4*>(smem);
    float4* __restrict__ xis = reinterpret_cast<float4*>(smem + XI_OFF);
    float4* __restrict__ thh = reinterpret_cast<float4*>(smem + TH_OFF);
    float2* __restrict__ vsh = reinterpret_cast<float2*>(smem + V_OFF);

    const int tid  = threadIdx.x;
    const int base = blockIdx.x * ROWS;

    const float4* __restrict__ X4  = reinterpret_cast<const float4*>(X);
    const float4* __restrict__ T4  = reinterpret_cast<const float4*>(theta);
    const float4* __restrict__ XI4 = reinterpret_cast<const float4*>(xi);

    const uint32_t sb = (uint32_t)__cvta_generic_to_shared(smem);

    int hrow = base + ROWS;
    if (hrow >= N) hrow -= N;

    // One-time smem fills (visible after first in-loop __syncthreads)
    xis[tid] = XI4[tid];                         // 64 threads cover all 64 units
    if (tid < 32)
        thh[tid] = T4[(size_t)hrow * 32 + tid];  // theta halo row

    // X-halo loads issued early; reduced at the very end (warp 0 only)
    float4 xh, hw0, hw1;
    if (tid < 32) {
        xh  = __ldg(X4 + (size_t)hrow * 32 + tid);
        hw0 = __ldg(XI4 + tid);
        hw1 = __ldg(XI4 + 32 + tid);
    }

    // Issue geometry: idx = tid + 64k -> row = r0 + 8k, u const,
    // (row & 7) == (r0 & 7) so the swizzle XOR is loop-invariant.
    const int r0 = tid >> 3;        // 0..7
    const int u  = tid & 7;
    const int su = u ^ (r0 & 7);

    auto issue = [&](int c, int s) {
        const float4* xsrc = X4 + (size_t)(base + r0) * 32 + c * UNITS + u;
        const float4* tsrc = T4 + (size_t)(base + r0) * 32 + c * UNITS + u;
        const uint32_t xd = sb + (uint32_t)s * STAGE_BYTES + (uint32_t)(r0 * UNITS + su) * 16;
        const uint32_t td = xd + (uint32_t)(ROWS * UNITS) * 16;   // +8192
        #pragma unroll
        for (int k = 0; k < 8; k++) {       // rows r0+8k, k=0..7 -> 64 rows
            cp_async16(xd + (uint32_t)k * 1024, xsrc + (size_t)k * 256);
            cp_async16(td + (uint32_t)k * 1024, tsrc + (size_t)k * 256);
        }
        cp_commit();
    };

    issue(0, 0);
    issue(1, 1);

    float pd = 0.0f, ps = 0.0f, q0 = 0.0f, q1 = 0.0f;

    const int mx = tid & 7;              // swizzle xor for x / theta-diag rows
    #pragma unroll
    for (int c = 0; c < NCHUNK; c++) {
        if (c < NCHUNK - 1) cp_wait<1>(); else cp_wait<0>();
        __syncthreads();

        const float4* __restrict__ st = buf + (c & 1) * STAGE_UNITS;
        const float4* __restrict__ xrow = st + tid * UNITS;
        const float4* __restrict__ trow = st + (ROWS + tid) * UNITS;

        const float4* sptr;
        int sxor;
        if (tid < ROWS - 1) { sptr = st + (ROWS + tid + 1) * UNITS; sxor = (tid + 1) & 7; }
        else                { sptr = thh + c * UNITS;               sxor = 0; }

        #pragma unroll
        for (int uu = 0; uu < UNITS; uu++) {
            float4 xv = xrow[uu ^ mx];
            float4 td = trow[uu ^ mx];
            float4 ts = sptr[uu ^ sxor];
            float4 w0 = xis[c * UNITS + uu];         // broadcast
            float4 w1 = xis[32 + c * UNITS + uu];    // broadcast
            acc4(pd, xv, td);
            acc4(ps, xv, ts);
            acc4(q0, xv, w0);
            acc4(q1, xv, w1);
        }

        __syncthreads();
        if (c + 2 < NCHUNK) issue(c + 2, c & 1);
    }

    // ---- Epilogue ----
    const float gb0 = g_bias[0];
    const float gb1 = g_bias[1];

    const int i = base + tid;
    int in = i + 1;
    if (in >= N) in -= N;

    const float wd = fmaxf(pd + __ldg(f_bias + i),  0.0f);
    const float ws = fmaxf(ps + __ldg(f_bias + in), 0.0f);
    const float v0 = fmaxf(q0 + gb0, 0.0f);
    const float v1 = fmaxf(q1 + gb1, 0.0f);
    vsh[tid] = make_float2(v0, v1);

    // Halo V (warp 0): loads were issued at kernel start
    if (tid < 32) {
        float h0 = dot4(xh, hw0);
        float h1 = dot4(xh, hw1);
        #pragma unroll
        for (int o = 16; o > 0; o >>= 1) {
            h0 += __shfl_xor_sync(0xFFFFFFFFu, h0, o);
            h1 += __shfl_xor_sync(0xFFFFFFFFu, h1, o);
        }
        if (tid == 0)
            vsh[ROWS] = make_float2(fmaxf(h0 + gb0, 0.0f), fmaxf(h1 + gb1, 0.0f));
    }
    __syncthreads();

    const float2 vn = vsh[tid + 1];
    float2 o;
    o.x = wd * v0 + ws * vn.x;
    o.y = wd * v1 + ws * vn.y;
    reinterpret_cast<float2*>(out)[i] = o;
}

extern "C" void kernel_launch(void* const* d_in, const int* in_sizes, int n_in,
                              void* d_out, int out_size)
{
    const float* X      = (const float*)d_in[0];
    const float* theta  = (const float*)d_in[1];
    const float* f_bias = (const float*)d_in[2];
    const float* xi     = (const float*)d_in[3];
    const float* g_bias = (const float*)d_in[4];
    float* out = (float*)d_out;

    const int N = in_sizes[2];            // f_bias has N elements
    const int blocks = N / ROWS;          // 524288 / 64 = 8192

    cudaFuncSetAttribute(smf_kernel,
                         cudaFuncAttributeMaxDynamicSharedMemorySize,
                         SMEM_TOTAL);

    smf_kernel<<<blocks, THREADS, SMEM_TOTAL>>>(X, theta, f_bias, xi, g_bias, out, N);
}